// round 2
// baseline (speedup 1.0000x reference)
#include <cuda_runtime.h>
#include <cuda_fp16.h>
#include <cstdint>

// ---------------------------------------------------------------------------
// Persistent fused 2-layer LSTM, fp16 tensor cores (mma.sync.m16n8k16, f32 acc)
// grid = 128 CTAs x 256 threads, each CTA owns 64 batch samples for all 28
// steps of both layers. States live in SMEM; weights stream from L2 in a
// pre-swizzled fragment layout built by a prep kernel.
// ---------------------------------------------------------------------------

#define NT      256
#define BTILE   64
#define NCTA    128
#define TSTEPS  28
#define HIDN    128
#define GATES   512
#define KT0     10          // K=160 (32-padded input | h0) / 16
#define KT1     16          // K=256 (h1 | h0) / 16
#define SA0_S   168         // halves per row (336B, %16B==0, conflict-free)
#define SA1_S   264         // halves per row (528B)
#define SACT_S  520         // halves per row (1040B)

#define OFF_A0   0
#define OFF_A1   (OFF_A0 + 64*SA0_S*2)        // 21504
#define OFF_ACT  (OFF_A1 + 64*SA1_S*2)        // 55296
#define OFF_C0   (OFF_ACT + 64*SACT_S*2)      // 121856
#define OFF_C1   (OFF_C0 + 64*HIDN*4)         // 154624
#define OFF_B0   (OFF_C1 + 64*HIDN*4)         // 187392
#define OFF_B1   (OFF_B0 + GATES*4)           // 189440
#define SMEM_BYTES (OFF_B1 + GATES*4)         // 191488

// device scratch (allowed: __device__ globals, no runtime allocation)
__device__ __align__(16) uint2 g_Wf0[64*KT0*32];   // [nsub][ktile][lane]{b0b1,b2b3}
__device__ __align__(16) uint2 g_Wf1[64*KT1*32];
__device__ float g_bias0[GATES];
__device__ float g_bias1[GATES];

// ---------------------------------------------------------------------------
__device__ __forceinline__ float ex2f(float x){ float y; asm("ex2.approx.f32 %0, %1;" : "=f"(y) : "f"(x)); return y; }
__device__ __forceinline__ float rcpf(float x){ float y; asm("rcp.approx.f32 %0, %1;" : "=f"(y) : "f"(x)); return y; }
__device__ __forceinline__ float fsigmoid(float x){ return rcpf(1.0f + ex2f(-1.4426950408889634f * x)); }
__device__ __forceinline__ float ftanh(float x){ return 1.0f - 2.0f * rcpf(1.0f + ex2f(2.8853900817779268f * x)); }

__device__ __forceinline__ void ldsm4(uint32_t* r, uint32_t addr) {
    asm volatile("ldmatrix.sync.aligned.m8n8.x4.shared.b16 {%0,%1,%2,%3}, [%4];"
                 : "=r"(r[0]), "=r"(r[1]), "=r"(r[2]), "=r"(r[3]) : "r"(addr));
}

__device__ __forceinline__ void mma16816(float* c, const uint32_t* a, const uint32_t* b) {
    asm volatile("mma.sync.aligned.m16n8k16.row.col.f32.f16.f16.f32 "
                 "{%0,%1,%2,%3}, {%4,%5,%6,%7}, {%8,%9}, {%0,%1,%2,%3};"
                 : "+f"(c[0]), "+f"(c[1]), "+f"(c[2]), "+f"(c[3])
                 : "r"(a[0]), "r"(a[1]), "r"(a[2]), "r"(a[3]), "r"(b[0]), "r"(b[1]));
}

__device__ __forceinline__ uint32_t pack2(float a, float b) {
    __half2 h = __floats2half2_rn(a, b);
    return *reinterpret_cast<uint32_t*>(&h);
}

// ---------------------------------------------------------------------------
// Prep: pack weights into fragment-linear fp16 layout + fuse biases.
// Combined W0[g][k]: k<28 -> w_ih0, 28..31 -> 0, 32..159 -> w_hh0[k-32]
// Combined W1[g][k]: k<128 -> w_hh1, 128..255 -> w_ih1[k-128]
// ---------------------------------------------------------------------------
__device__ __forceinline__ float w0val(const float* wih0, const float* whh0, int n, int k) {
    if (k < 28)  return wih0[n*28 + k];
    if (k < 32)  return 0.0f;
    return whh0[n*HIDN + (k - 32)];
}
__device__ __forceinline__ float w1val(const float* wih1, const float* whh1, int n, int k) {
    if (k < HIDN) return whh1[n*HIDN + k];
    return wih1[n*HIDN + (k - HIDN)];
}

__global__ void prep_kernel(const float* __restrict__ wih0, const float* __restrict__ whh0,
                            const float* __restrict__ bih0, const float* __restrict__ bhh0,
                            const float* __restrict__ wih1, const float* __restrict__ whh1,
                            const float* __restrict__ bih1, const float* __restrict__ bhh1) {
    int tid = blockIdx.x * blockDim.x + threadIdx.x;
    if (tid < GATES) {
        g_bias0[tid] = bih0[tid] + bhh0[tid];
        g_bias1[tid] = bih1[tid] + bhh1[tid];
    }
    // m16n8k16 B fragment (B is K x N, col spec): lane holds
    // b0=B[k][n], b1=B[k+1][n], b2=B[k+8][n], b3=B[k+9][n]
    // with k = ktile*16 + (lane%4)*2, n = nsub*8 + lane/4.
    if (tid < 64*KT0*32) {
        int lane = tid & 31;
        int kt   = (tid >> 5) % KT0;
        int ns   = tid / (32*KT0);
        int n = ns*8 + (lane >> 2);
        int k = kt*16 + (lane & 3)*2;
        uint2 u;
        u.x = pack2(w0val(wih0, whh0, n, k),     w0val(wih0, whh0, n, k+1));
        u.y = pack2(w0val(wih0, whh0, n, k+8),   w0val(wih0, whh0, n, k+9));
        g_Wf0[tid] = u;
    }
    if (tid < 64*KT1*32) {
        int lane = tid & 31;
        int kt   = (tid >> 5) % KT1;
        int ns   = tid / (32*KT1);
        int n = ns*8 + (lane >> 2);
        int k = kt*16 + (lane & 3)*2;
        uint2 u;
        u.x = pack2(w1val(wih1, whh1, n, k),     w1val(wih1, whh1, n, k+1));
        u.y = pack2(w1val(wih1, whh1, n, k+8),   w1val(wih1, whh1, n, k+9));
        g_Wf1[tid] = u;
    }
}

// ---------------------------------------------------------------------------
// GEMM + bias + activation into sAct.
// Warp w, pass p: gate columns n0 = p*256 + w*32 (disjoint across warps -> each
// weight fragment is loaded exactly once per CTA per step). Rows: all 64.
// ---------------------------------------------------------------------------
template<int KT>
__device__ __forceinline__ void loadBfrag(uint32_t (&b)[4][2], const uint2* __restrict__ Wf,
                                          int ns0, int kt, int lane) {
#pragma unroll
    for (int s = 0; s < 4; ++s) {
        uint2 v = Wf[((ns0 + s)*KT + kt)*32 + lane];
        b[s][0] = v.x; b[s][1] = v.y;
    }
}

template<int SAS>
__device__ __forceinline__ void loadAfrag(uint32_t (&a)[4][4], uint32_t aBase, int kt,
                                          int lrow, int lkoff) {
#pragma unroll
    for (int mt = 0; mt < 4; ++mt) {
        uint32_t addr = aBase + (uint32_t)(((mt*16 + lrow)*SAS + kt*16 + lkoff) * 2);
        ldsm4(a[mt], addr);
    }
}

template<int KT, int SAS>
__device__ __forceinline__ void gemm_act(const half* __restrict__ sA,
                                         const uint2* __restrict__ Wf,
                                         const float* __restrict__ sBias,
                                         half* __restrict__ sAct,
                                         int warp, int lane) {
    uint32_t aBase = (uint32_t)__cvta_generic_to_shared(sA);
    const int lrow  = lane & 15;
    const int lkoff = (lane >> 4) * 8;

    for (int pass = 0; pass < 2; ++pass) {
        const int n0  = pass*256 + warp*32;
        const int ns0 = n0 >> 3;

        float acc[4][4][4];
#pragma unroll
        for (int mt = 0; mt < 4; ++mt)
#pragma unroll
            for (int s = 0; s < 4; ++s)
#pragma unroll
                for (int q = 0; q < 4; ++q) acc[mt][s][q] = 0.0f;

        uint32_t breg[3][4][2];
        uint32_t areg[2][4][4];
        loadBfrag<KT>(breg[0], Wf, ns0, 0, lane);
        loadBfrag<KT>(breg[1], Wf, ns0, 1, lane);
        loadAfrag<SAS>(areg[0], aBase, 0, lrow, lkoff);

#pragma unroll
        for (int kt = 0; kt < KT; ++kt) {
            if (kt + 2 < KT) loadBfrag<KT>(breg[(kt+2)%3], Wf, ns0, kt+2, lane);
            if (kt + 1 < KT) loadAfrag<SAS>(areg[(kt+1)&1], aBase, kt+1, lrow, lkoff);
#pragma unroll
            for (int mt = 0; mt < 4; ++mt)
#pragma unroll
                for (int s = 0; s < 4; ++s)
                    mma16816(acc[mt][s], areg[kt&1][mt], breg[kt%3][s]);
        }

        // epilogue: + bias, activation by gate block, store fp16 to sAct
#pragma unroll
        for (int mt = 0; mt < 4; ++mt) {
#pragma unroll
            for (int s = 0; s < 4; ++s) {
                int col  = n0 + s*8 + (lane & 3)*2;
                int gate = col >> 7;                 // 0:i 1:f 2:g 3:o
                float b0 = sBias[col], b1 = sBias[col+1];
                int r0 = mt*16 + (lane >> 2);
                float v0 = acc[mt][s][0] + b0, v1 = acc[mt][s][1] + b1;
                float v2 = acc[mt][s][2] + b0, v3 = acc[mt][s][3] + b1;
                if (gate == 2) { v0 = ftanh(v0); v1 = ftanh(v1); v2 = ftanh(v2); v3 = ftanh(v3); }
                else           { v0 = fsigmoid(v0); v1 = fsigmoid(v1); v2 = fsigmoid(v2); v3 = fsigmoid(v3); }
                *(__half2*)&sAct[(size_t)r0*SACT_S + col]       = __floats2half2_rn(v0, v1);
                *(__half2*)&sAct[(size_t)(r0+8)*SACT_S + col]   = __floats2half2_rn(v2, v3);
            }
        }
    }
}

// ---------------------------------------------------------------------------
__global__ __launch_bounds__(NT, 1)
void lstm_kernel(const float* __restrict__ x, const float* __restrict__ w_out,
                 const float* __restrict__ b_out, float* __restrict__ out) {
    extern __shared__ char smem[];
    half*  sA0  = (half*)(smem + OFF_A0);    // [64][168]: cols 0..31 x_t (pad), 32..159 h0
    half*  sA1  = (half*)(smem + OFF_A1);    // [64][264]: cols 0..127 h1, 128..255 h0
    half*  sAct = (half*)(smem + OFF_ACT);   // [64][520]: activated gates
    float* c0   = (float*)(smem + OFF_C0);
    float* c1   = (float*)(smem + OFF_C1);
    float* sB0  = (float*)(smem + OFF_B0);
    float* sB1  = (float*)(smem + OFF_B1);

    const int tid  = threadIdx.x;
    const int warp = tid >> 5;
    const int lane = tid & 31;

    // init: zero states (h0, h1, c, x-pad)
    for (int i = tid; i < 64*SA0_S; i += NT) ((unsigned short*)sA0)[i] = 0;
    for (int i = tid; i < 64*SA1_S; i += NT) ((unsigned short*)sA1)[i] = 0;
    for (int i = tid; i < 64*HIDN;  i += NT) { c0[i] = 0.0f; c1[i] = 0.0f; }
    for (int i = tid; i < GATES;    i += NT) { sB0[i] = g_bias0[i]; sB1[i] = g_bias1[i]; }
    __syncthreads();

    const float* xb = x + (size_t)blockIdx.x * BTILE * 784;

    for (int t = 0; t < TSTEPS; ++t) {
        // load x_t slice -> fp16 into sA0 cols 0..27 (28..31 stay zero)
        for (int i = tid; i < BTILE*28; i += NT) {
            int r = i / 28, c = i - r*28;
            sA0[r*SA0_S + c] = __float2half(xb[(size_t)r*784 + t*28 + c]);
        }
        __syncthreads();

        // layer 0: gates = act([x_t | h0] @ W0^T + b0)
        gemm_act<KT0, SA0_S>(sA0, g_Wf0, sB0, sAct, warp, lane);
        __syncthreads();

        // elementwise layer 0: c0, h0 -> sA0(cols 32..) and sA1(cols 128..)
        for (int i = tid; i < BTILE*HIDN; i += NT) {
            int n = i >> 7, j = i & 127;
            const half* ar = sAct + (size_t)n*SACT_S;
            float ig = __half2float(ar[j]);
            float fg = __half2float(ar[j+128]);
            float gg = __half2float(ar[j+256]);
            float og = __half2float(ar[j+384]);
            float cc = fmaf(fg, c0[i], ig*gg);
            c0[i] = cc;
            half h = __float2half(og * ftanh(cc));
            sA0[n*SA0_S + 32 + j]  = h;
            sA1[n*SA1_S + 128 + j] = h;
        }
        __syncthreads();

        // layer 1: gates = act([h1 | h0] @ [w_hh1|w_ih1]^T + b1)
        gemm_act<KT1, SA1_S>(sA1, g_Wf1, sB1, sAct, warp, lane);
        __syncthreads();

        // elementwise layer 1: c1, h1 -> sA1(cols 0..127)
        for (int i = tid; i < BTILE*HIDN; i += NT) {
            int n = i >> 7, j = i & 127;
            const half* ar = sAct + (size_t)n*SACT_S;
            float ig = __half2float(ar[j]);
            float fg = __half2float(ar[j+128]);
            float gg = __half2float(ar[j+256]);
            float og = __half2float(ar[j+384]);
            float cc = fmaf(fg, c1[i], ig*gg);
            c1[i] = cc;
            sA1[n*SA1_S + j] = __float2half(og * ftanh(cc));
        }
        __syncthreads();
    }

    // output head: out[n][o] = h1_final . w_out[o] + b_out[o]
    const size_t ng0 = (size_t)blockIdx.x * BTILE;
    for (int i = tid; i < BTILE*10; i += NT) {
        int n = i / 10, o = i - n*10;
        float s = b_out[o];
        const half* hr = sA1 + (size_t)n*SA1_S;
#pragma unroll 8
        for (int j = 0; j < HIDN; ++j)
            s = fmaf(__half2float(hr[j]), w_out[o*HIDN + j], s);
        out[(ng0 + n)*10 + o] = s;
    }
}

// ---------------------------------------------------------------------------
extern "C" void kernel_launch(void* const* d_in, const int* in_sizes, int n_in,
                              void* d_out, int out_size) {
    const float* x     = (const float*)d_in[0];
    const float* wih0  = (const float*)d_in[1];
    const float* whh0  = (const float*)d_in[2];
    const float* bih0  = (const float*)d_in[3];
    const float* bhh0  = (const float*)d_in[4];
    const float* wih1  = (const float*)d_in[5];
    const float* whh1  = (const float*)d_in[6];
    const float* bih1  = (const float*)d_in[7];
    const float* bhh1  = (const float*)d_in[8];
    const float* w_out = (const float*)d_in[9];
    const float* b_out = (const float*)d_in[10];

    cudaFuncSetAttribute(lstm_kernel, cudaFuncAttributeMaxDynamicSharedMemorySize, SMEM_BYTES);

    prep_kernel<<<128, NT>>>(wih0, whh0, bih0, bhh0, wih1, whh1, bih1, bhh1);
    lstm_kernel<<<NCTA, NT, SMEM_BYTES>>>(x, w_out, b_out, (float*)d_out);
}

// round 7
// speedup vs baseline: 2.0120x; 2.0120x over previous
#include <cuda_runtime.h>
#include <cuda_fp16.h>
#include <cstdint>

// ---------------------------------------------------------------------------
// Persistent fused 2-layer LSTM, fp16 tensor cores, FUSED cell update.
// Gate-major column remap: each warp-pass computes {i,f,g,o} x 8 j-columns so
// the full LSTM cell update runs in the GEMM epilogue (no sAct, no separate
// elementwise phases, 2 barriers/step instead of 4). h double-buffered in
// SMEM; c in conflict-free lane-interleaved SMEM.
// ---------------------------------------------------------------------------

#define NT      256
#define BTILE   64
#define NCTA    128
#define TSTEPS  28
#define HIDN    128
#define GATES   512
#define KT0     10          // K=160 (32-padded x | h0) / 16
#define KT1     16          // K=256 (h1 | h0) / 16
#define SA0_S   168         // halves per row
#define SA1_S   264

#define A0_HALVES (64*SA0_S)                 // 10752 per buffer
#define A1_HALVES (64*SA1_S)                 // 16896 per buffer

#define OFF_A0   0
#define OFF_A1   (OFF_A0 + 2*A0_HALVES*2)    // 43008
#define OFF_C0   (OFF_A1 + 2*A1_HALVES*2)    // 110592
#define OFF_C1   (OFF_C0 + 64*HIDN*4)        // 143360
#define OFF_B0   (OFF_C1 + 64*HIDN*4)        // 176128
#define OFF_B1   (OFF_B0 + GATES*4)          // 178176
#define SMEM_BYTES (OFF_B1 + GATES*4)        // 180224

// fragment-packed weights: [jb(16)][gate(4)][kt][lane(32)] -> linear = tid order
__device__ __align__(16) uint2 g_Wf0[16*4*KT0*32];
__device__ __align__(16) uint2 g_Wf1[16*4*KT1*32];
__device__ float g_bias0[GATES];
__device__ float g_bias1[GATES];

// ---------------------------------------------------------------------------
__device__ __forceinline__ __half2 lh2tanh(__half2 x) {
    __half2 y;
    asm("tanh.approx.f16x2 %0, %1;" : "=r"(*(uint32_t*)&y) : "r"(*(uint32_t*)&x));
    return y;
}

__device__ __forceinline__ void ldsm4(uint32_t* r, uint32_t addr) {
    asm volatile("ldmatrix.sync.aligned.m8n8.x4.shared.b16 {%0,%1,%2,%3}, [%4];"
                 : "=r"(r[0]), "=r"(r[1]), "=r"(r[2]), "=r"(r[3]) : "r"(addr));
}

__device__ __forceinline__ void mma16816(float* c, const uint32_t* a, const uint32_t* b) {
    asm volatile("mma.sync.aligned.m16n8k16.row.col.f32.f16.f16.f32 "
                 "{%0,%1,%2,%3}, {%4,%5,%6,%7}, {%8,%9}, {%0,%1,%2,%3};"
                 : "+f"(c[0]), "+f"(c[1]), "+f"(c[2]), "+f"(c[3])
                 : "r"(a[0]), "r"(a[1]), "r"(a[2]), "r"(a[3]), "r"(b[0]), "r"(b[1]));
}

__device__ __forceinline__ uint32_t pack2(float a, float b) {
    __half2 h = __floats2half2_rn(a, b);
    return *reinterpret_cast<uint32_t*>(&h);
}

// ---------------------------------------------------------------------------
// Prep: pack weights into gate-major fragment layout + fuse biases.
// Global column n = gate*128 + jb*8 + (lane>>2); k = kt*16 + (lane&3)*2.
// W0[n][k]: k<28 -> w_ih0, 28..31 -> 0, 32..159 -> w_hh0[k-32]
// W1[n][k]: k<128 -> w_hh1, else w_ih1[k-128]
// ---------------------------------------------------------------------------
__device__ __forceinline__ float w0val(const float* wih0, const float* whh0, int n, int k) {
    if (k < 28)  return wih0[n*28 + k];
    if (k < 32)  return 0.0f;
    return whh0[n*HIDN + (k - 32)];
}
__device__ __forceinline__ float w1val(const float* wih1, const float* whh1, int n, int k) {
    if (k < HIDN) return whh1[n*HIDN + k];
    return wih1[n*HIDN + (k - HIDN)];
}

__global__ void prep_kernel(const float* __restrict__ wih0, const float* __restrict__ whh0,
                            const float* __restrict__ bih0, const float* __restrict__ bhh0,
                            const float* __restrict__ wih1, const float* __restrict__ whh1,
                            const float* __restrict__ bih1, const float* __restrict__ bhh1) {
    int tid = blockIdx.x * blockDim.x + threadIdx.x;
    if (tid < GATES) {
        g_bias0[tid] = bih0[tid] + bhh0[tid];
        g_bias1[tid] = bih1[tid] + bhh1[tid];
    }
    if (tid < 16*4*KT0*32) {
        int lane = tid & 31;
        int kt   = (tid >> 5) % KT0;
        int r    = tid / (32*KT0);
        int gate = r & 3, jb = r >> 2;
        int n = gate*128 + jb*8 + (lane >> 2);
        int k = kt*16 + (lane & 3)*2;
        uint2 u;
        u.x = pack2(w0val(wih0, whh0, n, k),   w0val(wih0, whh0, n, k+1));
        u.y = pack2(w0val(wih0, whh0, n, k+8), w0val(wih0, whh0, n, k+9));
        g_Wf0[tid] = u;
    }
    if (tid < 16*4*KT1*32) {
        int lane = tid & 31;
        int kt   = (tid >> 5) % KT1;
        int r    = tid / (32*KT1);
        int gate = r & 3, jb = r >> 2;
        int n = gate*128 + jb*8 + (lane >> 2);
        int k = kt*16 + (lane & 3)*2;
        uint2 u;
        u.x = pack2(w1val(wih1, whh1, n, k),   w1val(wih1, whh1, n, k+1));
        u.y = pack2(w1val(wih1, whh1, n, k+8), w1val(wih1, whh1, n, k+9));
        g_Wf1[tid] = u;
    }
}

// ---------------------------------------------------------------------------
// Fused LSTM epilogue: acc[mt][gate][q] -> activations -> c update -> h stores
// sB: biases, 0.5-prescaled for i/f/o gates, raw for g.
// cW: per-warp c slice, layout [cellIdx][lane] (conflict-free).
// ---------------------------------------------------------------------------
template<bool DUAL>
__device__ __forceinline__ void lstm_epilogue(
    float (&acc)[4][4][4], const float* __restrict__ sB, float* __restrict__ cW,
    int passBase, int jb,
    half* __restrict__ dA, int strA, int offA,
    half* __restrict__ dB, int strB, int offB, int lane)
{
    const int j0 = jb*8 + (lane & 3)*2;
    const float2 bI = *(const float2*)&sB[        j0];
    const float2 bF = *(const float2*)&sB[128   + j0];
    const float2 bG = *(const float2*)&sB[256   + j0];
    const float2 bO = *(const float2*)&sB[384   + j0];
    const __half2 H05 = __float2half2_rn(0.5f);
#pragma unroll
    for (int mt = 0; mt < 4; ++mt) {
        const int r0 = mt*16 + (lane >> 2);
#pragma unroll
        for (int hq = 0; hq < 2; ++hq) {
            const int row = r0 + hq*8;
            const float aI0 = acc[mt][0][2*hq], aI1 = acc[mt][0][2*hq+1];
            const float aF0 = acc[mt][1][2*hq], aF1 = acc[mt][1][2*hq+1];
            const float aG0 = acc[mt][2][2*hq], aG1 = acc[mt][2][2*hq+1];
            const float aO0 = acc[mt][3][2*hq], aO1 = acc[mt][3][2*hq+1];
            // sigmoid(x) = 0.5*tanh(0.5x)+0.5 ; biases prescaled by 0.5 for i/f/o
            __half2 TI = lh2tanh(__floats2half2_rn(fmaf(aI0,0.5f,bI.x), fmaf(aI1,0.5f,bI.y)));
            __half2 TF = lh2tanh(__floats2half2_rn(fmaf(aF0,0.5f,bF.x), fmaf(aF1,0.5f,bF.y)));
            __half2 TG = lh2tanh(__floats2half2_rn(aG0 + bG.x,          aG1 + bG.y));
            __half2 TO = lh2tanh(__floats2half2_rn(fmaf(aO0,0.5f,bO.x), fmaf(aO1,0.5f,bO.y)));
            __half2 SI = __hfma2(TI, H05, H05);
            __half2 SF = __hfma2(TF, H05, H05);
            __half2 SO = __hfma2(TO, H05, H05);
            float2 fI = __half22float2(SI);
            float2 fF = __half22float2(SF);
            float2 fG = __half22float2(TG);
            const int ci = passBase + mt*4 + hq*2;
            float c0 = cW[ci*32 + lane];
            float c1 = cW[(ci+1)*32 + lane];
            c0 = fmaf(fF.x, c0, fI.x * fG.x);
            c1 = fmaf(fF.y, c1, fI.y * fG.y);
            cW[ci*32 + lane]     = c0;
            cW[(ci+1)*32 + lane] = c1;
            __half2 H = __hmul2(SO, lh2tanh(__floats2half2_rn(c0, c1)));
            *(__half2*)&dA[row*strA + offA + j0] = H;
            if (DUAL) *(__half2*)&dB[row*strB + offB + j0] = H;
        }
    }
}

// ---------------------------------------------------------------------------
// One layer: GEMM (2 passes unified into one 2*KT k-stream with depth-3 B
// prefetch crossing the pass boundary) + fused epilogue per pass.
// Internal __syncthreads placed AFTER the first B prefetches (hides L2 lat).
// ---------------------------------------------------------------------------
template<int KT, int SAS, bool DUAL>
__device__ __forceinline__ void gemm_layer(
    const half* __restrict__ sA, const uint2* __restrict__ Wf,
    const float* __restrict__ sB, float* __restrict__ cW,
    half* __restrict__ dA, int strA, int offA,
    half* __restrict__ dB, int strB, int offB,
    int warp, int lane)
{
    const uint32_t aBase = (uint32_t)__cvta_generic_to_shared(sA);
    const int lrow  = lane & 15;
    const int lkoff = (lane >> 4) * 8;
    const uint2* W0 = Wf + (size_t)((0*8 + warp)*4*KT)*32 + lane;
    const uint2* W1 = Wf + (size_t)((1*8 + warp)*4*KT)*32 + lane;

    uint32_t breg[4][4][2];
    uint32_t areg[2][4][4];
    float acc[4][4][4];

    auto loadB = [&](int u) {
        const int pass = (u >= KT) ? 1 : 0;
        const int kt   = u - pass*KT;
        const uint2* p = pass ? W1 : W0;
#pragma unroll
        for (int s = 0; s < 4; ++s) {
            uint2 v = p[(s*KT + kt)*32];
            breg[u & 3][s][0] = v.x;
            breg[u & 3][s][1] = v.y;
        }
    };
    auto loadA = [&](int u) {
        const int kt = (u >= KT) ? (u - KT) : u;
#pragma unroll
        for (int mt = 0; mt < 4; ++mt)
            ldsm4(areg[u & 1][mt],
                  aBase + (uint32_t)(((mt*16 + lrow)*SAS + kt*16 + lkoff) * 2));
    };

    loadB(0); loadB(1); loadB(2);
    __syncthreads();               // covers all producer writes of this step
    loadA(0);

#pragma unroll
    for (int mt = 0; mt < 4; ++mt)
#pragma unroll
        for (int s = 0; s < 4; ++s)
#pragma unroll
            for (int q = 0; q < 4; ++q) acc[mt][s][q] = 0.0f;

#pragma unroll
    for (int u = 0; u < 2*KT; ++u) {
        if (u + 3 < 2*KT) loadB(u + 3);
        if (u + 1 < 2*KT) loadA(u + 1);
#pragma unroll
        for (int mt = 0; mt < 4; ++mt)
#pragma unroll
            for (int s = 0; s < 4; ++s)
                mma16816(acc[mt][s], areg[u & 1][mt], breg[u & 3][s]);
        if (u == KT - 1) {
            lstm_epilogue<DUAL>(acc, sB, cW, 0, warp, dA, strA, offA, dB, strB, offB, lane);
#pragma unroll
            for (int mt = 0; mt < 4; ++mt)
#pragma unroll
                for (int s = 0; s < 4; ++s)
#pragma unroll
                    for (int q = 0; q < 4; ++q) acc[mt][s][q] = 0.0f;
        }
    }
    lstm_epilogue<DUAL>(acc, sB, cW, 16, 8 + warp, dA, strA, offA, dB, strB, offB, lane);
}

// ---------------------------------------------------------------------------
__global__ __launch_bounds__(NT, 1)
void lstm_kernel(const float* __restrict__ x, const float* __restrict__ w_out,
                 const float* __restrict__ b_out, float* __restrict__ out) {
    extern __shared__ char smem[];
    half*  A0 = (half*)(smem + OFF_A0);   // 2 buffers [64][168]: 0..31 x(+pad), 32..159 h0
    half*  A1 = (half*)(smem + OFF_A1);   // 2 buffers [64][264]: 0..127 h1, 128..255 h0
    float* C0 = (float*)(smem + OFF_C0);  // [warp][cell][lane]
    float* C1 = (float*)(smem + OFF_C1);
    float* sB0 = (float*)(smem + OFF_B0);
    float* sB1 = (float*)(smem + OFF_B1);

    const int tid  = threadIdx.x;
    const int warp = tid >> 5;
    const int lane = tid & 31;
    float* c0W = C0 + warp*1024;
    float* c1W = C1 + warp*1024;

    // init: zero states + x pad, scaled biases
    for (int i = tid; i < 2*A0_HALVES; i += NT) ((unsigned short*)A0)[i] = 0;
    for (int i = tid; i < 2*A1_HALVES; i += NT) ((unsigned short*)A1)[i] = 0;
    for (int i = tid; i < 64*HIDN; i += NT) { C0[i] = 0.0f; C1[i] = 0.0f; }
    for (int i = tid; i < GATES; i += NT) {
        float b0 = g_bias0[i], b1 = g_bias1[i];
        bool gg = ((i >> 7) == 2);
        sB0[i] = gg ? b0 : 0.5f*b0;
        sB1[i] = gg ? b1 : 0.5f*b1;
    }

    const float* xb = x + (size_t)blockIdx.x * BTILE * 784;

    half* a0r = A0;             half* a0w = A0 + A0_HALVES;
    half* a1r = A1;             half* a1w = A1 + A1_HALVES;

    // x(0) into the first read buffer
    for (int i = tid; i < BTILE*28; i += NT) {
        int r = i / 28, c = i - r*28;
        a0r[r*SA0_S + c] = __float2half(xb[(size_t)r*784 + 0*28 + c]);
    }
    // (visibility covered by the sync inside the first gemm_layer)

    for (int t = 0; t < TSTEPS; ++t) {
        // layer 0: reads a0r; writes h0 -> a0w (cols 32..) and a1r (cols 128..)
        gemm_layer<KT0, SA0_S, true>(a0r, g_Wf0, sB0, c0W,
                                     a0w, SA0_S, 32, a1r, SA1_S, 128, warp, lane);
        // stage x(t+1) into a0w (no reader until after next barrier)
        if (t + 1 < TSTEPS) {
            for (int i = tid; i < BTILE*28; i += NT) {
                int r = i / 28, c = i - r*28;
                a0w[r*SA0_S + c] = __float2half(xb[(size_t)r*784 + (t+1)*28 + c]);
            }
        }
        // layer 1: reads a1r; writes h1 -> a1w (cols 0..127)
        gemm_layer<KT1, SA1_S, false>(a1r, g_Wf1, sB1, c1W,
                                      a1w, SA1_S, 0, (half*)0, 0, 0, warp, lane);
        half* tmp;
        tmp = a0r; a0r = a0w; a0w = tmp;
        tmp = a1r; a1r = a1w; a1w = tmp;
    }
    __syncthreads();

    // output head: out[n][o] = h1_final . w_out[o] + b_out[o]
    const size_t ng0 = (size_t)blockIdx.x * BTILE;
    for (int i = tid; i < BTILE*10; i += NT) {
        int n = i / 10, o = i - n*10;
        float s = b_out[o];
        const half* hr = a1r + (size_t)n*SA1_S;
#pragma unroll 8
        for (int j = 0; j < HIDN; ++j)
            s = fmaf(__half2float(hr[j]), w_out[o*HIDN + j], s);
        out[(ng0 + n)*10 + o] = s;
    }
}

// ---------------------------------------------------------------------------
extern "C" void kernel_launch(void* const* d_in, const int* in_sizes, int n_in,
                              void* d_out, int out_size) {
    const float* x     = (const float*)d_in[0];
    const float* wih0  = (const float*)d_in[1];
    const float* whh0  = (const float*)d_in[2];
    const float* bih0  = (const float*)d_in[3];
    const float* bhh0  = (const float*)d_in[4];
    const float* wih1  = (const float*)d_in[5];
    const float* whh1  = (const float*)d_in[6];
    const float* bih1  = (const float*)d_in[7];
    const float* bhh1  = (const float*)d_in[8];
    const float* w_out = (const float*)d_in[9];
    const float* b_out = (const float*)d_in[10];

    cudaFuncSetAttribute(lstm_kernel, cudaFuncAttributeMaxDynamicSharedMemorySize, SMEM_BYTES);

    prep_kernel<<<128, NT>>>(wih0, whh0, bih0, bhh0, wih1, whh1, bih1, bhh1);
    lstm_kernel<<<NCTA, NT, SMEM_BYTES>>>(x, w_out, b_out, (float*)d_out);
}

// round 13
// speedup vs baseline: 3.2253x; 1.6030x over previous
#include <cuda_runtime.h>
#include <cuda_fp16.h>
#include <cstdint>

// ---------------------------------------------------------------------------
// Persistent fused 2-layer LSTM, fp16 tensor cores, FUSED cell update.
// 512 threads / 16 warps per CTA: each warp owns ONE jb tile (4 gates x 8 j)
// for all 64 rows -> 4 warps/SMSP for latency hiding. B prefetch uses a
// 3-deep ring (depth-2 lookahead) -- (kt+2)%3 never aliases kt%3.
// ---------------------------------------------------------------------------

#define NT      512
#define BTILE   64
#define NCTA    128
#define TSTEPS  28
#define HIDN    128
#define GATES   512
#define KT0     10          // K=160 (32-padded x | h0) / 16
#define KT1     16          // K=256 (h1 | h0) / 16
#define SA0_S   168         // halves per row
#define SA1_S   264

#define A0_HALVES (64*SA0_S)                 // 10752 per buffer
#define A1_HALVES (64*SA1_S)                 // 16896 per buffer

#define OFF_A0   0
#define OFF_A1   (OFF_A0 + 2*A0_HALVES*2)    // 43008
#define OFF_C0   (OFF_A1 + 2*A1_HALVES*2)    // 110592
#define OFF_C1   (OFF_C0 + 64*HIDN*4)        // 143360
#define OFF_B0   (OFF_C1 + 64*HIDN*4)        // 176128
#define OFF_B1   (OFF_B0 + GATES*4)          // 178176
#define SMEM_BYTES (OFF_B1 + GATES*4)        // 180224

// fragment-packed weights: [jb(16)][gate(4)][kt][lane(32)] -> linear = tid order
__device__ __align__(16) uint2 g_Wf0[16*4*KT0*32];
__device__ __align__(16) uint2 g_Wf1[16*4*KT1*32];
__device__ float g_bias0[GATES];
__device__ float g_bias1[GATES];

// ---------------------------------------------------------------------------
__device__ __forceinline__ __half2 lh2tanh(__half2 x) {
    __half2 y;
    asm("tanh.approx.f16x2 %0, %1;" : "=r"(*(uint32_t*)&y) : "r"(*(uint32_t*)&x));
    return y;
}

__device__ __forceinline__ void ldsm4(uint32_t* r, uint32_t addr) {
    asm volatile("ldmatrix.sync.aligned.m8n8.x4.shared.b16 {%0,%1,%2,%3}, [%4];"
                 : "=r"(r[0]), "=r"(r[1]), "=r"(r[2]), "=r"(r[3]) : "r"(addr));
}

__device__ __forceinline__ void mma16816(float* c, const uint32_t* a, const uint32_t* b) {
    asm volatile("mma.sync.aligned.m16n8k16.row.col.f32.f16.f16.f32 "
                 "{%0,%1,%2,%3}, {%4,%5,%6,%7}, {%8,%9}, {%0,%1,%2,%3};"
                 : "+f"(c[0]), "+f"(c[1]), "+f"(c[2]), "+f"(c[3])
                 : "r"(a[0]), "r"(a[1]), "r"(a[2]), "r"(a[3]), "r"(b[0]), "r"(b[1]));
}

__device__ __forceinline__ uint32_t pack2(float a, float b) {
    __half2 h = __floats2half2_rn(a, b);
    return *reinterpret_cast<uint32_t*>(&h);
}

// ---------------------------------------------------------------------------
// Prep: pack weights into gate-major fragment layout + fuse biases.
// Global column n = gate*128 + jb*8 + (lane>>2); k = kt*16 + (lane&3)*2.
// W0[n][k]: k<28 -> w_ih0, 28..31 -> 0, 32..159 -> w_hh0[k-32]
// W1[n][k]: k<128 -> w_hh1, else w_ih1[k-128]
// ---------------------------------------------------------------------------
__device__ __forceinline__ float w0val(const float* wih0, const float* whh0, int n, int k) {
    if (k < 28)  return wih0[n*28 + k];
    if (k < 32)  return 0.0f;
    return whh0[n*HIDN + (k - 32)];
}
__device__ __forceinline__ float w1val(const float* wih1, const float* whh1, int n, int k) {
    if (k < HIDN) return whh1[n*HIDN + k];
    return wih1[n*HIDN + (k - HIDN)];
}

__global__ void prep_kernel(const float* __restrict__ wih0, const float* __restrict__ whh0,
                            const float* __restrict__ bih0, const float* __restrict__ bhh0,
                            const float* __restrict__ wih1, const float* __restrict__ whh1,
                            const float* __restrict__ bih1, const float* __restrict__ bhh1) {
    int tid = blockIdx.x * blockDim.x + threadIdx.x;
    if (tid < GATES) {
        g_bias0[tid] = bih0[tid] + bhh0[tid];
        g_bias1[tid] = bih1[tid] + bhh1[tid];
    }
    if (tid < 16*4*KT0*32) {
        int lane = tid & 31;
        int kt   = (tid >> 5) % KT0;
        int r    = tid / (32*KT0);
        int gate = r & 3, jb = r >> 2;
        int n = gate*128 + jb*8 + (lane >> 2);
        int k = kt*16 + (lane & 3)*2;
        uint2 u;
        u.x = pack2(w0val(wih0, whh0, n, k),   w0val(wih0, whh0, n, k+1));
        u.y = pack2(w0val(wih0, whh0, n, k+8), w0val(wih0, whh0, n, k+9));
        g_Wf0[tid] = u;
    }
    if (tid < 16*4*KT1*32) {
        int lane = tid & 31;
        int kt   = (tid >> 5) % KT1;
        int r    = tid / (32*KT1);
        int gate = r & 3, jb = r >> 2;
        int n = gate*128 + jb*8 + (lane >> 2);
        int k = kt*16 + (lane & 3)*2;
        uint2 u;
        u.x = pack2(w1val(wih1, whh1, n, k),   w1val(wih1, whh1, n, k+1));
        u.y = pack2(w1val(wih1, whh1, n, k+8), w1val(wih1, whh1, n, k+9));
        g_Wf1[tid] = u;
    }
}

// ---------------------------------------------------------------------------
// Fused LSTM epilogue: acc[mt][gate][q] -> activations -> c update -> h stores
// sB: biases, 0.5-prescaled for i/f/o gates, raw for g.
// cW: per-warp c slice (16 cells x 32 lanes), conflict-free.
// ---------------------------------------------------------------------------
template<bool DUAL>
__device__ __forceinline__ void lstm_epilogue(
    float (&acc)[4][4][4], const float* __restrict__ sB, float* __restrict__ cW,
    int jb,
    half* __restrict__ dA, int strA, int offA,
    half* __restrict__ dB, int strB, int offB, int lane)
{
    const int j0 = jb*8 + (lane & 3)*2;
    const float2 bI = *(const float2*)&sB[        j0];
    const float2 bF = *(const float2*)&sB[128   + j0];
    const float2 bG = *(const float2*)&sB[256   + j0];
    const float2 bO = *(const float2*)&sB[384   + j0];
    const __half2 H05 = __float2half2_rn(0.5f);
#pragma unroll
    for (int mt = 0; mt < 4; ++mt) {
        const int r0 = mt*16 + (lane >> 2);
#pragma unroll
        for (int hq = 0; hq < 2; ++hq) {
            const int row = r0 + hq*8;
            const float aI0 = acc[mt][0][2*hq], aI1 = acc[mt][0][2*hq+1];
            const float aF0 = acc[mt][1][2*hq], aF1 = acc[mt][1][2*hq+1];
            const float aG0 = acc[mt][2][2*hq], aG1 = acc[mt][2][2*hq+1];
            const float aO0 = acc[mt][3][2*hq], aO1 = acc[mt][3][2*hq+1];
            // sigmoid(x) = 0.5*tanh(0.5x)+0.5 ; biases prescaled by 0.5 for i/f/o
            __half2 TI = lh2tanh(__floats2half2_rn(fmaf(aI0,0.5f,bI.x), fmaf(aI1,0.5f,bI.y)));
            __half2 TF = lh2tanh(__floats2half2_rn(fmaf(aF0,0.5f,bF.x), fmaf(aF1,0.5f,bF.y)));
            __half2 TG = lh2tanh(__floats2half2_rn(aG0 + bG.x,          aG1 + bG.y));
            __half2 TO = lh2tanh(__floats2half2_rn(fmaf(aO0,0.5f,bO.x), fmaf(aO1,0.5f,bO.y)));
            __half2 SI = __hfma2(TI, H05, H05);
            __half2 SF = __hfma2(TF, H05, H05);
            __half2 SO = __hfma2(TO, H05, H05);
            float2 fI = __half22float2(SI);
            float2 fF = __half22float2(SF);
            float2 fG = __half22float2(TG);
            const int ci = mt*4 + hq*2;
            float c0 = cW[ci*32 + lane];
            float c1 = cW[(ci+1)*32 + lane];
            c0 = fmaf(fF.x, c0, fI.x * fG.x);
            c1 = fmaf(fF.y, c1, fI.y * fG.y);
            cW[ci*32 + lane]     = c0;
            cW[(ci+1)*32 + lane] = c1;
            __half2 H = __hmul2(SO, lh2tanh(__floats2half2_rn(c0, c1)));
            *(__half2*)&dA[row*strA + offA + j0] = H;
            if (DUAL) *(__half2*)&dB[row*strB + offB + j0] = H;
        }
    }
}

// ---------------------------------------------------------------------------
// One layer: single-pass GEMM per warp (jb = warp), depth-2 B prefetch into a
// 3-deep ring, single-buffered A fragments (cross-warp latency hiding at 4
// warps/SMSP). __syncthreads placed AFTER the first B prefetches.
// ---------------------------------------------------------------------------
template<int KT, int SAS, bool DUAL>
__device__ __forceinline__ void gemm_layer(
    const half* __restrict__ sA, const uint2* __restrict__ Wf,
    const float* __restrict__ sB, float* __restrict__ cW,
    half* __restrict__ dA, int strA, int offA,
    half* __restrict__ dB, int strB, int offB,
    int warp, int lane)
{
    const uint32_t aBase = (uint32_t)__cvta_generic_to_shared(sA);
    const int lrow  = lane & 15;
    const int lkoff = (lane >> 4) * 8;
    const uint2* W = Wf + (size_t)(warp*4*KT)*32 + lane;

    uint32_t breg[3][4][2];
    uint32_t areg[4][4];
    float acc[4][4][4];

    auto loadB = [&](int kt) {
        const int slot = kt % 3;
#pragma unroll
        for (int s = 0; s < 4; ++s) {
            uint2 v = W[(s*KT + kt)*32];
            breg[slot][s][0] = v.x;
            breg[slot][s][1] = v.y;
        }
    };

    loadB(0); loadB(1);
    __syncthreads();               // covers all producer writes of this step

#pragma unroll
    for (int mt = 0; mt < 4; ++mt)
#pragma unroll
        for (int s = 0; s < 4; ++s)
#pragma unroll
            for (int q = 0; q < 4; ++q) acc[mt][s][q] = 0.0f;

#pragma unroll
    for (int kt = 0; kt < KT; ++kt) {
        // A fragments for this kt (consumed below; gap filled by other warps)
#pragma unroll
        for (int mt = 0; mt < 4; ++mt)
            ldsm4(areg[mt],
                  aBase + (uint32_t)(((mt*16 + lrow)*SAS + kt*16 + lkoff) * 2));
        if (kt + 2 < KT) loadB(kt + 2);   // (kt+2)%3 != kt%3 and != (kt+1)%3
#pragma unroll
        for (int mt = 0; mt < 4; ++mt)
#pragma unroll
            for (int s = 0; s < 4; ++s)
                mma16816(acc[mt][s], areg[mt], breg[kt % 3][s]);
    }
    lstm_epilogue<DUAL>(acc, sB, cW, warp, dA, strA, offA, dB, strB, offB, lane);
}

// ---------------------------------------------------------------------------
__global__ __launch_bounds__(NT, 1)
void lstm_kernel(const float* __restrict__ x, const float* __restrict__ w_out,
                 const float* __restrict__ b_out, float* __restrict__ out) {
    extern __shared__ char smem[];
    half*  A0 = (half*)(smem + OFF_A0);   // 2 buffers [64][168]: 0..31 x(+pad), 32..159 h0
    half*  A1 = (half*)(smem + OFF_A1);   // 2 buffers [64][264]: 0..127 h1, 128..255 h0
    float* C0 = (float*)(smem + OFF_C0);  // [warp][cell][lane]
    float* C1 = (float*)(smem + OFF_C1);
    float* sB0 = (float*)(smem + OFF_B0);
    float* sB1 = (float*)(smem + OFF_B1);

    const int tid  = threadIdx.x;
    const int warp = tid >> 5;
    const int lane = tid & 31;
    float* c0W = C0 + warp*512;
    float* c1W = C1 + warp*512;

    // init: zero states + x pad, scaled biases
    for (int i = tid; i < 2*A0_HALVES; i += NT) ((unsigned short*)A0)[i] = 0;
    for (int i = tid; i < 2*A1_HALVES; i += NT) ((unsigned short*)A1)[i] = 0;
    for (int i = tid; i < 64*HIDN; i += NT) { C0[i] = 0.0f; C1[i] = 0.0f; }
    for (int i = tid; i < GATES; i += NT) {
        float b0 = g_bias0[i], b1 = g_bias1[i];
        bool gg = ((i >> 7) == 2);
        sB0[i] = gg ? b0 : 0.5f*b0;
        sB1[i] = gg ? b1 : 0.5f*b1;
    }

    const float* xb = x + (size_t)blockIdx.x * BTILE * 784;

    half* a0r = A0;             half* a0w = A0 + A0_HALVES;
    half* a1r = A1;             half* a1w = A1 + A1_HALVES;

    // x(0) into the first read buffer
    for (int i = tid; i < BTILE*28; i += NT) {
        int r = i / 28, c = i - r*28;
        a0r[r*SA0_S + c] = __float2half(xb[(size_t)r*784 + 0*28 + c]);
    }
    // (visibility covered by the sync inside the first gemm_layer)

    for (int t = 0; t < TSTEPS; ++t) {
        // layer 0: reads a0r; writes h0 -> a0w (cols 32..) and a1r (cols 128..)
        gemm_layer<KT0, SA0_S, true>(a0r, g_Wf0, sB0, c0W,
                                     a0w, SA0_S, 32, a1r, SA1_S, 128, warp, lane);
        // stage x(t+1) into a0w (no reader until after next barrier)
        if (t + 1 < TSTEPS) {
            for (int i = tid; i < BTILE*28; i += NT) {
                int r = i / 28, c = i - r*28;
                a0w[r*SA0_S + c] = __float2half(xb[(size_t)r*784 + (t+1)*28 + c]);
            }
        }
        // layer 1: reads a1r; writes h1 -> a1w (cols 0..127)
        gemm_layer<KT1, SA1_S, false>(a1r, g_Wf1, sB1, c1W,
                                      a1w, SA1_S, 0, (half*)0, 0, 0, warp, lane);
        half* tmp;
        tmp = a0r; a0r = a0w; a0w = tmp;
        tmp = a1r; a1r = a1w; a1w = tmp;
    }
    __syncthreads();

    // output head: out[n][o] = h1_final . w_out[o] + b_out[o]
    const size_t ng0 = (size_t)blockIdx.x * BTILE;
    for (int i = tid; i < BTILE*10; i += NT) {
        int n = i / 10, o = i - n*10;
        float s = b_out[o];
        const half* hr = a1r + (size_t)n*SA1_S;
#pragma unroll 8
        for (int j = 0; j < HIDN; ++j)
            s = fmaf(__half2float(hr[j]), w_out[o*HIDN + j], s);
        out[(ng0 + n)*10 + o] = s;
    }
}

// ---------------------------------------------------------------------------
extern "C" void kernel_launch(void* const* d_in, const int* in_sizes, int n_in,
                              void* d_out, int out_size) {
    const float* x     = (const float*)d_in[0];
    const float* wih0  = (const float*)d_in[1];
    const float* whh0  = (const float*)d_in[2];
    const float* bih0  = (const float*)d_in[3];
    const float* bhh0  = (const float*)d_in[4];
    const float* wih1  = (const float*)d_in[5];
    const float* whh1  = (const float*)d_in[6];
    const float* bih1  = (const float*)d_in[7];
    const float* bhh1  = (const float*)d_in[8];
    const float* w_out = (const float*)d_in[9];
    const float* b_out = (const float*)d_in[10];

    cudaFuncSetAttribute(lstm_kernel, cudaFuncAttributeMaxDynamicSharedMemorySize, SMEM_BYTES);

    prep_kernel<<<128, 256>>>(wih0, whh0, bih0, bhh0, wih1, whh1, bih1, bhh1);
    lstm_kernel<<<NCTA, NT, SMEM_BYTES>>>(x, w_out, b_out, (float*)d_out);
}